// round 15
// baseline (speedup 1.0000x reference)
#include <cuda_runtime.h>
#include <math.h>

#define NUM_NODES   2000000
#define NUM_MOVABLE 1500000
#define NUM_FILLER  400000
#define NUM_NETS    1500000
#define NUM_PINS    6000000
#define NB          512
#define NBP         513          // padded dim for diff map
#define BIN_W       1.953125f
#define UNIT_CAP    1.5f
#define EPSF        1e-6f

// ---------------- scratch (static device globals; no allocations) -----------
__device__ float2 g_pin_xy[NUM_PINS];   // interleaved (x,y) per physical pin
__device__ float2 g_D[NBP * NBP];       // diff map [y*NBP + x], padded
__device__ float2 g_Sf[NB * NB];        // scan_x result [y*NB + x] (float2)
__device__ float  g_ratio[NB * NB];     // ratio map [x*NB + y]
__device__ double g_sum_area;
__device__ double g_sum_route;
__device__ double g_sum_filler;
__device__ unsigned int g_bar;          // device-wide barrier counter

__device__ __forceinline__ int bin_of(float v) {
    int b = (int)floorf(v / BIN_W);
    return min(max(b, 0), NB - 1);
}

// one L2 atomic op for the adjacent (dh, dv) pair
__device__ __forceinline__ void red2(float2* addr, float a, float b) {
    asm volatile("red.global.add.v2.f32 [%0], {%1, %2};"
                 :: "l"(addr), "f"(a), "f"(b) : "memory");
}

// ---------------- kernel 1: pin transpose + zero scratch --------------------
#define PIN_GROUPS (NUM_PINS / 4)          // 1.5M
__global__ void k_prep(const float4* __restrict__ px4,
                       const float4* __restrict__ py4) {
    int g = blockIdx.x * blockDim.x + threadIdx.x;
    if (g < PIN_GROUPS) {
        float4 x = px4[g];
        float4 y = py4[g];
        float4* out = (float4*)g_pin_xy;
        out[g * 2]     = make_float4(x.x, y.x, x.y, y.y);
        out[g * 2 + 1] = make_float4(x.z, y.z, x.w, y.w);
    }
    if (g < NBP * NBP) g_D[g] = make_float2(0.0f, 0.0f);
    if (g == 0) {
        g_sum_area   = 0.0;
        g_sum_route  = 0.0;
        g_sum_filler = 0.0;
        g_bar        = 0u;
    }
}

// ---------------- kernel 2: fused nets-scatter + area/filler sums -----------
#define NET_PER_THREAD 2
#define NET_THREADS    (NUM_NETS / NET_PER_THREAD)          // 750000
#define NET_BLOCKS     ((NET_THREADS + 255) / 256)          // 2930
#define AREA_GROUPS    (NUM_NODES / 4)                      // 500000
#define AREA_BLOCKS    ((AREA_GROUPS + 255) / 256)          // 1954

__device__ __forceinline__ void net_scatter(int4 fp) {
    float2 p0 = __ldg(&g_pin_xy[fp.x]);
    float2 p1 = __ldg(&g_pin_xy[fp.y]);
    float2 p2 = __ldg(&g_pin_xy[fp.z]);
    float2 p3 = __ldg(&g_pin_xy[fp.w]);

    float xl = fminf(fminf(p0.x, p1.x), fminf(p2.x, p3.x));
    float xh = fmaxf(fmaxf(p0.x, p1.x), fmaxf(p2.x, p3.x));
    float yl = fminf(fminf(p0.y, p1.y), fminf(p2.y, p3.y));
    float yh = fmaxf(fmaxf(p0.y, p1.y), fmaxf(p2.y, p3.y));

    float bw = xh - xl;
    float bh = yh - yl;
    float barea = fmaxf(bw * bh, EPSF);
    float dh = bw / barea;
    float dv = bh / barea;

    int blx = bin_of(xl);
    int bhx = bin_of(xh) + 1;   // up to 512: lands in padding (never read)
    int bly = bin_of(yl);
    int bhy = bin_of(yh) + 1;

    red2(&g_D[bly * NBP + blx],  dh,  dv);
    red2(&g_D[bly * NBP + bhx], -dh, -dv);
    red2(&g_D[bhy * NBP + blx], -dh, -dv);
    red2(&g_D[bhy * NBP + bhx],  dh,  dv);
}

__global__ void k_fused(const int* __restrict__ flat_netpin,
                        const float4* __restrict__ nsx4,
                        const float4* __restrict__ nsy4) {
    if (blockIdx.x < NET_BLOCKS) {
        int gid = blockIdx.x * blockDim.x + threadIdx.x;
        int n0 = gid * NET_PER_THREAD;
        if (n0 >= NUM_NETS) return;
        const int4* fp4 = (const int4*)flat_netpin;
        int4 a = fp4[n0];
        int4 b = fp4[n0 + 1];
        net_scatter(a);
        net_scatter(b);
        return;
    }

    // ---- area/filler sums (no atomics to bin grids; no pos reads) ----
    int g = (blockIdx.x - NET_BLOCKS) * blockDim.x + threadIdx.x;
    double la = 0.0, lf = 0.0;
    if (g < AREA_GROUPS) {
        int i0 = g * 4;
        float4 sx = nsx4[g];
        float4 sy = nsy4[g];
        float s = (double)0.0;
        float a0 = sx.x * sy.x, a1 = sx.y * sy.y;
        float a2 = sx.z * sy.z, a3 = sx.w * sy.w;
        double tot = (double)a0 + (double)a1 + (double)a2 + (double)a3;
        (void)s;
        if (i0 < NUM_MOVABLE) {
            la = tot;
        } else if (i0 >= NUM_NODES - NUM_FILLER) {
            lf = tot;
        }
    }
    for (int off = 16; off > 0; off >>= 1) {
        la += __shfl_down_sync(0xFFFFFFFFu, la, off);
        lf += __shfl_down_sync(0xFFFFFFFFu, lf, off);
    }
    if ((threadIdx.x & 31) == 0) {
        if (la != 0.0) atomicAdd(&g_sum_area,   la);
        if (lf != 0.0) atomicAdd(&g_sum_filler, lf);
    }
}

// ---------------- block-wide inclusive scan (512 threads, double2) ----------
__device__ __forceinline__ double2 block_scan_512(double2 v) {
    __shared__ double2 partials[16];
    int lane = threadIdx.x & 31;
    int warp = threadIdx.x >> 5;
    #pragma unroll
    for (int off = 1; off < 32; off <<= 1) {
        double ax = __shfl_up_sync(0xFFFFFFFFu, v.x, off);
        double ay = __shfl_up_sync(0xFFFFFFFFu, v.y, off);
        if (lane >= off) { v.x += ax; v.y += ay; }
    }
    if (lane == 31) partials[warp] = v;
    __syncthreads();
    if (warp == 0 && lane < 16) {
        double2 p = partials[lane];
        #pragma unroll
        for (int off = 1; off < 16; off <<= 1) {
            double ax = __shfl_up_sync(0x0000FFFFu, p.x, off);
            double ay = __shfl_up_sync(0x0000FFFFu, p.y, off);
            if (lane >= off) { p.x += ax; p.y += ay; }
        }
        partials[lane] = p;
    }
    __syncthreads();
    if (warp > 0) {
        double2 p = partials[warp - 1];
        v.x += p.x; v.y += p.y;
    }
    return v;
}

__device__ __forceinline__ void device_barrier(int target) {
    if (threadIdx.x == 0) {
        __threadfence();
        atomicAdd(&g_bar, 1u);
        while (atomicAdd(&g_bar, 0u) < (unsigned)target) __nanosleep(64);
        __threadfence();
    }
    __syncthreads();
}

// ---------------- kernel 3: scan_x | scan_y+ratio | route-dot ---------------
// 512 blocks x 512 threads, all co-resident (<=32 regs via launch_bounds).
#define MOV_GROUPS (NUM_MOVABLE / 4)       // 375000
#define SCAN_THREADS (NB * NB)             // 262144

__global__ void __launch_bounds__(512, 4) k_scan(
        const float4* __restrict__ pos4,
        const float4* __restrict__ posy4,
        const float4* __restrict__ nsx4,
        const float4* __restrict__ nsy4) {
    int b = blockIdx.x;
    int t = threadIdx.x;

    // ---- phase 1: inclusive scan along x for row y=b (fully coalesced) ----
    {
        float2 d = g_D[b * NBP + t];
        double2 v = make_double2((double)d.x, (double)d.y);
        v = block_scan_512(v);
        g_Sf[b * NB + t] = make_float2((float)v.x, (float)v.y);
    }
    __syncthreads();
    device_barrier(NB);

    // ---- phase 2: scan along y for column x=b -> ratio map ----
    {
        float2 d = g_Sf[t * NB + b];
        double2 v = make_double2((double)d.x, (double)d.y);
        v = block_scan_512(v);
        float uh = (float)v.x / UNIT_CAP;
        float uv = (float)v.y / UNIT_CAP;
        float r = fminf(fmaxf(fmaxf(uh, uv), 0.5f), 2.0f);
        g_ratio[b * NB + t] = r;
    }
    __syncthreads();
    device_barrier(2 * NB);

    // ---- phase 3: sum_route = sum over movable nodes of area*ratio ----
    {
        __shared__ double s_route[16];
        int lane = t & 31;
        int warp = t >> 5;
        double lr = 0.0;
        int tid = b * 512 + t;
        #pragma unroll
        for (int it = 0; it < 2; it++) {
            int g = tid + it * SCAN_THREADS;
            if (g < MOV_GROUPS) {
                float4 x  = pos4[g];
                float4 y  = posy4[g];
                float4 sx = nsx4[g];
                float4 sy = nsy4[g];
                int i0 = bin_of(x.x + 0.5f * sx.x) * NB + bin_of(y.x + 0.5f * sy.x);
                int i1 = bin_of(x.y + 0.5f * sx.y) * NB + bin_of(y.y + 0.5f * sy.y);
                int i2 = bin_of(x.z + 0.5f * sx.z) * NB + bin_of(y.z + 0.5f * sy.z);
                int i3 = bin_of(x.w + 0.5f * sx.w) * NB + bin_of(y.w + 0.5f * sy.w);
                float r0 = __ldg(&g_ratio[i0]);
                float r1 = __ldg(&g_ratio[i1]);
                float r2 = __ldg(&g_ratio[i2]);
                float r3 = __ldg(&g_ratio[i3]);
                lr += (double)(sx.x * sy.x * r0) + (double)(sx.y * sy.y * r1)
                    + (double)(sx.z * sy.z * r2) + (double)(sx.w * sy.w * r3);
            }
        }
        for (int off = 16; off > 0; off >>= 1)
            lr += __shfl_down_sync(0xFFFFFFFFu, lr, off);
        if (lane == 0) s_route[warp] = lr;
        __syncthreads();
        if (warp == 0) {
            double tt = (lane < 16) ? s_route[lane] : 0.0;
            for (int off = 8; off > 0; off >>= 1)
                tt += __shfl_down_sync(0xFFFFFFFFu, tt, off);
            if (lane == 0 && tt != 0.0) atomicAdd(&g_sum_route, tt);
        }
    }
}

// ---------------- kernel 4: outputs (float4, inline scalars) ----------------
#define OUT_GROUPS (NUM_NODES / 4)        // 500000

__global__ void __launch_bounds__(256, 8)
k_output(const float4* __restrict__ pos4,
         const float4* __restrict__ posy4,
         const float4* __restrict__ nsx4,
         const float4* __restrict__ nsy4,
         float4* __restrict__ out) {
    int g = blockIdx.x * blockDim.x + threadIdx.x;
    if (g >= OUT_GROUPS) return;
    int i0 = g * 4;

    // scalars from global sums (uniform broadcast loads)
    float sum_area   = (float)g_sum_area;
    float sum_route  = (float)g_sum_route;
    float sum_filler = (float)g_sum_filler;
    float max_total  = sum_area + sum_filler;
    float scale  = fminf(1.0f, max_total / fmaxf(sum_route, EPSF));
    float fscale = sqrtf(fmaxf(max_total - sum_route * scale, 0.0f) /
                         fmaxf(sum_filler, EPSF));

    float4 x  = pos4[g];
    float4 y  = posy4[g];
    float4 sx = nsx4[g];
    float4 sy = nsy4[g];

    float4 xo = x, yo = y, sxo = sx, syo = sy;

    if (i0 < NUM_MOVABLE) {
        int r0i = bin_of(x.x + 0.5f * sx.x) * NB + bin_of(y.x + 0.5f * sy.x);
        int r1i = bin_of(x.y + 0.5f * sx.y) * NB + bin_of(y.y + 0.5f * sy.y);
        int r2i = bin_of(x.z + 0.5f * sx.z) * NB + bin_of(y.z + 0.5f * sy.z);
        int r3i = bin_of(x.w + 0.5f * sx.w) * NB + bin_of(y.w + 0.5f * sy.w);
        float r0 = __ldg(&g_ratio[r0i]);
        float r1 = __ldg(&g_ratio[r1i]);
        float r2 = __ldg(&g_ratio[r2i]);
        float r3 = __ldg(&g_ratio[r3i]);

        float s0 = sqrtf(r0 * scale), s1 = sqrtf(r1 * scale);
        float s2 = sqrtf(r2 * scale), s3 = sqrtf(r3 * scale);
        float nx0 = sx.x * s0, ny0 = sy.x * s0;
        float nx1 = sx.y * s1, ny1 = sy.y * s1;
        float nx2 = sx.z * s2, ny2 = sy.z * s2;
        float nx3 = sx.w * s3, ny3 = sy.w * s3;
        xo.x = x.x + 0.5f * (sx.x - nx0); yo.x = y.x + 0.5f * (sy.x - ny0);
        xo.y = x.y + 0.5f * (sx.y - nx1); yo.y = y.y + 0.5f * (sy.y - ny1);
        xo.z = x.z + 0.5f * (sx.z - nx2); yo.z = y.z + 0.5f * (sy.z - ny2);
        xo.w = x.w + 0.5f * (sx.w - nx3); yo.w = y.w + 0.5f * (sy.w - ny3);
        sxo = make_float4(nx0, nx1, nx2, nx3);
        syo = make_float4(ny0, ny1, ny2, ny3);
    } else if (i0 >= NUM_NODES - NUM_FILLER) {
        sxo.x = sx.x * fscale; sxo.y = sx.y * fscale;
        sxo.z = sx.z * fscale; sxo.w = sx.w * fscale;
        syo.x = sy.x * fscale; syo.y = sy.y * fscale;
        syo.z = sy.z * fscale; syo.w = sy.w * fscale;
    }

    out[g]                  = xo;
    out[OUT_GROUPS + g]     = yo;
    out[2 * OUT_GROUPS + g] = sxo;
    out[3 * OUT_GROUPS + g] = syo;
}

// ---------------- launch -----------------------------------------------------
extern "C" void kernel_launch(void* const* d_in, const int* in_sizes, int n_in,
                              void* d_out, int out_size) {
    const float* pos         = (const float*)d_in[0];
    const float* pin_pos     = (const float*)d_in[1];
    const float* node_size_x = (const float*)d_in[2];
    const float* node_size_y = (const float*)d_in[3];
    const int*   flat_netpin = (const int*)d_in[4];
    float* out = (float*)d_out;

    const float4* pos4  = (const float4*)pos;
    const float4* posy4 = (const float4*)(pos + NUM_NODES);
    const float4* nsx4  = (const float4*)node_size_x;
    const float4* nsy4  = (const float4*)node_size_y;
    const float4* px4   = (const float4*)pin_pos;
    const float4* py4   = (const float4*)(pin_pos + NUM_PINS);

    k_prep<<<(PIN_GROUPS + 255) / 256, 256>>>(px4, py4);
    k_fused<<<NET_BLOCKS + AREA_BLOCKS, 256>>>(flat_netpin, nsx4, nsy4);
    k_scan<<<NB, NB>>>(pos4, posy4, nsx4, nsy4);
    k_output<<<(OUT_GROUPS + 255) / 256, 256>>>(pos4, posy4, nsx4, nsy4,
                                                (float4*)out);
}

// round 16
// speedup vs baseline: 1.0713x; 1.0713x over previous
#include <cuda_runtime.h>
#include <math.h>

#define NUM_NODES   2000000
#define NUM_MOVABLE 1500000
#define NUM_FILLER  400000
#define NUM_NETS    1500000
#define NUM_PINS    6000000
#define NB          512
#define NBP         513          // padded dim for diff map
#define BIN_W       1.953125f
#define UNIT_CAP    1.5f
#define EPSF        1e-6f

// ---------------- scratch (static device globals; no allocations) -----------
__device__ float2 g_pin_xy[NUM_PINS];   // interleaved (x,y) per physical pin
__device__ float2 g_D[NBP * NBP];       // diff map [y*NBP + x], padded
__device__ float2 g_Sf[NB * NB];        // scan_x result [y*NB + x] (float2)
__device__ float  g_ratio[NB * NB];     // ratio map [x*NB + y]
__device__ float  g_binarea[NB * NB];   // per-bin movable area [x*NB + y]
__device__ double g_sum_area;
__device__ double g_sum_route;
__device__ double g_sum_filler;
__device__ unsigned int g_bar;          // device-wide barrier counter

__device__ __forceinline__ int bin_of(float v) {
    int b = (int)floorf(v / BIN_W);
    return min(max(b, 0), NB - 1);
}

// one L2 atomic op for the adjacent (dh, dv) pair
__device__ __forceinline__ void red2(float2* addr, float a, float b) {
    asm volatile("red.global.add.v2.f32 [%0], {%1, %2};"
                 :: "l"(addr), "f"(a), "f"(b) : "memory");
}

// ---------------- kernel 1: pin transpose + zero scratch --------------------
#define PIN_GROUPS (NUM_PINS / 4)          // 1.5M
__global__ void k_prep(const float4* __restrict__ px4,
                       const float4* __restrict__ py4) {
    int g = blockIdx.x * blockDim.x + threadIdx.x;
    if (g < PIN_GROUPS) {
        float4 x = px4[g];
        float4 y = py4[g];
        float4* out = (float4*)g_pin_xy;
        out[g * 2]     = make_float4(x.x, y.x, x.y, y.y);
        out[g * 2 + 1] = make_float4(x.z, y.z, x.w, y.w);
    }
    if (g < NBP * NBP) g_D[g] = make_float2(0.0f, 0.0f);
    if (g < NB * NB)   g_binarea[g] = 0.0f;
    if (g == 0) {
        g_sum_area   = 0.0;
        g_sum_route  = 0.0;
        g_sum_filler = 0.0;
        g_bar        = 0u;
    }
}

// ---------------- kernel 2: fused nets-scatter + node sums (PDL dep) --------
#define NET_PER_THREAD 2
#define NET_THREADS    (NUM_NETS / NET_PER_THREAD)          // 750000
#define NET_BLOCKS     ((NET_THREADS + 255) / 256)          // 2930
#define AREA_GROUPS    (NUM_NODES / 4)                      // 500000
#define AREA_BLOCKS    ((AREA_GROUPS + 255) / 256)          // 1954

__device__ __forceinline__ void net_scatter(int4 fp) {
    float2 p0 = __ldg(&g_pin_xy[fp.x]);
    float2 p1 = __ldg(&g_pin_xy[fp.y]);
    float2 p2 = __ldg(&g_pin_xy[fp.z]);
    float2 p3 = __ldg(&g_pin_xy[fp.w]);

    float xl = fminf(fminf(p0.x, p1.x), fminf(p2.x, p3.x));
    float xh = fmaxf(fmaxf(p0.x, p1.x), fmaxf(p2.x, p3.x));
    float yl = fminf(fminf(p0.y, p1.y), fminf(p2.y, p3.y));
    float yh = fmaxf(fmaxf(p0.y, p1.y), fmaxf(p2.y, p3.y));

    float bw = xh - xl;
    float bh = yh - yl;
    float barea = fmaxf(bw * bh, EPSF);
    float dh = bw / barea;
    float dv = bh / barea;

    int blx = bin_of(xl);
    int bhx = bin_of(xh) + 1;   // up to 512: lands in padding (never read)
    int bly = bin_of(yl);
    int bhy = bin_of(yh) + 1;

    red2(&g_D[bly * NBP + blx],  dh,  dv);
    red2(&g_D[bly * NBP + bhx], -dh, -dv);
    red2(&g_D[bhy * NBP + blx], -dh, -dv);
    red2(&g_D[bhy * NBP + bhx],  dh,  dv);
}

__global__ void k_fused(const int* __restrict__ flat_netpin,
                        const float4* __restrict__ pos4,
                        const float4* __restrict__ posy4,
                        const float4* __restrict__ nsx4,
                        const float4* __restrict__ nsy4) {
    if (blockIdx.x < NET_BLOCKS) {
        int gid = blockIdx.x * blockDim.x + threadIdx.x;
        int n0 = gid * NET_PER_THREAD;
        // prelude: netpin indices are inputs, independent of k_prep
        int4 a = make_int4(0, 0, 0, 0), b = make_int4(0, 0, 0, 0);
        if (n0 < NUM_NETS) {
            const int4* fp4 = (const int4*)flat_netpin;
            a = fp4[n0];
            b = fp4[n0 + 1];
        }
        cudaGridDependencySynchronize();   // wait for g_pin_xy / g_D
        if (n0 >= NUM_NETS) return;
        net_scatter(a);
        net_scatter(b);
        return;
    }

    // ---- area part: prelude loads inputs, sync before scratch atomics ----
    int g = (blockIdx.x - NET_BLOCKS) * blockDim.x + threadIdx.x;
    double la = 0.0, lf = 0.0;
    float a0 = 0.f, a1 = 0.f, a2 = 0.f, a3 = 0.f;
    int b0 = 0, b1 = 0, b2 = 0, b3 = 0;
    bool movable = false;
    if (g < AREA_GROUPS) {
        int i0 = g * 4;
        float4 sx = nsx4[g];
        float4 sy = nsy4[g];
        if (i0 < NUM_MOVABLE) {
            float4 px = pos4[g];
            float4 py = posy4[g];
            a0 = sx.x * sy.x; a1 = sx.y * sy.y;
            a2 = sx.z * sy.z; a3 = sx.w * sy.w;
            b0 = bin_of(px.x + 0.5f * sx.x) * NB + bin_of(py.x + 0.5f * sy.x);
            b1 = bin_of(px.y + 0.5f * sx.y) * NB + bin_of(py.y + 0.5f * sy.y);
            b2 = bin_of(px.z + 0.5f * sx.z) * NB + bin_of(py.z + 0.5f * sy.z);
            b3 = bin_of(px.w + 0.5f * sx.w) * NB + bin_of(py.w + 0.5f * sy.w);
            la = (double)a0 + (double)a1 + (double)a2 + (double)a3;
            movable = true;
        } else if (i0 >= NUM_NODES - NUM_FILLER) {
            lf = (double)(sx.x * sy.x) + (double)(sx.y * sy.y)
               + (double)(sx.z * sy.z) + (double)(sx.w * sy.w);
        }
    }
    cudaGridDependencySynchronize();   // wait for zeroed g_binarea / sums
    if (movable) {
        atomicAdd(&g_binarea[b0], a0);
        atomicAdd(&g_binarea[b1], a1);
        atomicAdd(&g_binarea[b2], a2);
        atomicAdd(&g_binarea[b3], a3);
    }
    for (int off = 16; off > 0; off >>= 1) {
        la += __shfl_down_sync(0xFFFFFFFFu, la, off);
        lf += __shfl_down_sync(0xFFFFFFFFu, lf, off);
    }
    if ((threadIdx.x & 31) == 0) {
        if (la != 0.0) atomicAdd(&g_sum_area,   la);
        if (lf != 0.0) atomicAdd(&g_sum_filler, lf);
    }
}

// ---------------- block-wide inclusive scan (512 threads, double2) ----------
__device__ __forceinline__ double2 block_scan_512(double2 v) {
    __shared__ double2 partials[16];
    int lane = threadIdx.x & 31;
    int warp = threadIdx.x >> 5;
    #pragma unroll
    for (int off = 1; off < 32; off <<= 1) {
        double ax = __shfl_up_sync(0xFFFFFFFFu, v.x, off);
        double ay = __shfl_up_sync(0xFFFFFFFFu, v.y, off);
        if (lane >= off) { v.x += ax; v.y += ay; }
    }
    if (lane == 31) partials[warp] = v;
    __syncthreads();
    if (warp == 0 && lane < 16) {
        double2 p = partials[lane];
        #pragma unroll
        for (int off = 1; off < 16; off <<= 1) {
            double ax = __shfl_up_sync(0x0000FFFFu, p.x, off);
            double ay = __shfl_up_sync(0x0000FFFFu, p.y, off);
            if (lane >= off) { p.x += ax; p.y += ay; }
        }
        partials[lane] = p;
    }
    __syncthreads();
    if (warp > 0) {
        double2 p = partials[warp - 1];
        v.x += p.x; v.y += p.y;
    }
    return v;
}

// ---------------- kernel 3: merged scan_x + scan_y (one wave + barrier) -----
__global__ void __launch_bounds__(512, 4) k_scan() {
    cudaGridDependencySynchronize();   // wait for g_D / g_binarea
    int b = blockIdx.x;
    int t = threadIdx.x;

    // ---- phase 1: inclusive scan along x for row y=b (fully coalesced) ----
    {
        float2 d = g_D[b * NBP + t];
        double2 v = make_double2((double)d.x, (double)d.y);
        v = block_scan_512(v);
        g_Sf[b * NB + t] = make_float2((float)v.x, (float)v.y);
    }
    __syncthreads();

    // ---- device-wide barrier (threadfence-reduction pattern) ----
    if (t == 0) {
        __threadfence();
        atomicAdd(&g_bar, 1u);
        while (atomicAdd(&g_bar, 0u) < NB) __nanosleep(64);
        __threadfence();
    }
    __syncthreads();

    // ---- phase 2: scan along y for column x=b + ratio + dot ----
    {
        __shared__ double s_route[16];
        int x = b;
        int y = t;
        int lane = t & 31;
        int warp = t >> 5;

        float2 d = g_Sf[y * NB + x];
        double2 v = make_double2((double)d.x, (double)d.y);
        v = block_scan_512(v);
        float uh = (float)v.x / UNIT_CAP;
        float uv = (float)v.y / UNIT_CAP;
        float r = fminf(fmaxf(fmaxf(uh, uv), 0.5f), 2.0f);
        int idx = x * NB + y;
        g_ratio[idx] = r;

        // ratio is written; allow k_output to launch and run its prelude.
        // (all blocks are past the spin barrier here -> no residency deadlock)
        cudaTriggerProgrammaticLaunchCompletion();

        double lr = (double)(r * g_binarea[idx]);
        for (int off = 16; off > 0; off >>= 1)
            lr += __shfl_down_sync(0xFFFFFFFFu, lr, off);
        if (lane == 0) s_route[warp] = lr;
        __syncthreads();
        if (warp == 0) {
            double tt = (lane < 16) ? s_route[lane] : 0.0;
            for (int off = 8; off > 0; off >>= 1)
                tt += __shfl_down_sync(0xFFFFFFFFu, tt, off);
            if (lane == 0 && tt != 0.0) atomicAdd(&g_sum_route, tt);
        }
    }
}

// ---------------- kernel 4: outputs (prelude loads, then sync) --------------
#define OUT_GROUPS (NUM_NODES / 4)        // 500000

__global__ void k_output(const float4* __restrict__ pos4,
                         const float4* __restrict__ posy4,
                         const float4* __restrict__ nsx4,
                         const float4* __restrict__ nsy4,
                         float4* __restrict__ out) {
    int g = blockIdx.x * blockDim.x + threadIdx.x;
    bool live = (g < OUT_GROUPS);
    int i0 = g * 4;

    // prelude: pure-input loads + bin index math (independent of k_scan)
    float4 x = make_float4(0, 0, 0, 0), y = x, sx = x, sy = x;
    int r0i = 0, r1i = 0, r2i = 0, r3i = 0;
    if (live) {
        x  = pos4[g];
        y  = posy4[g];
        sx = nsx4[g];
        sy = nsy4[g];
        if (i0 < NUM_MOVABLE) {
            r0i = bin_of(x.x + 0.5f * sx.x) * NB + bin_of(y.x + 0.5f * sy.x);
            r1i = bin_of(x.y + 0.5f * sx.y) * NB + bin_of(y.y + 0.5f * sy.y);
            r2i = bin_of(x.z + 0.5f * sx.z) * NB + bin_of(y.z + 0.5f * sy.z);
            r3i = bin_of(x.w + 0.5f * sx.w) * NB + bin_of(y.w + 0.5f * sy.w);
        }
    }

    cudaGridDependencySynchronize();   // wait for g_ratio + sums
    if (!live) return;

    float sum_area   = (float)g_sum_area;
    float sum_route  = (float)g_sum_route;
    float sum_filler = (float)g_sum_filler;
    float max_total  = sum_area + sum_filler;
    float scale  = fminf(1.0f, max_total / fmaxf(sum_route, EPSF));
    float fscale = sqrtf(fmaxf(max_total - sum_route * scale, 0.0f) /
                         fmaxf(sum_filler, EPSF));

    float4 xo = x, yo = y, sxo = sx, syo = sy;

    if (i0 < NUM_MOVABLE) {
        float r0 = __ldg(&g_ratio[r0i]);
        float r1 = __ldg(&g_ratio[r1i]);
        float r2 = __ldg(&g_ratio[r2i]);
        float r3 = __ldg(&g_ratio[r3i]);

        float s0 = sqrtf(r0 * scale), s1 = sqrtf(r1 * scale);
        float s2 = sqrtf(r2 * scale), s3 = sqrtf(r3 * scale);
        float nx0 = sx.x * s0, ny0 = sy.x * s0;
        float nx1 = sx.y * s1, ny1 = sy.y * s1;
        float nx2 = sx.z * s2, ny2 = sy.z * s2;
        float nx3 = sx.w * s3, ny3 = sy.w * s3;
        xo.x = x.x + 0.5f * (sx.x - nx0); yo.x = y.x + 0.5f * (sy.x - ny0);
        xo.y = x.y + 0.5f * (sx.y - nx1); yo.y = y.y + 0.5f * (sy.y - ny1);
        xo.z = x.z + 0.5f * (sx.z - nx2); yo.z = y.z + 0.5f * (sy.z - ny2);
        xo.w = x.w + 0.5f * (sx.w - nx3); yo.w = y.w + 0.5f * (sy.w - ny3);
        sxo = make_float4(nx0, nx1, nx2, nx3);
        syo = make_float4(ny0, ny1, ny2, ny3);
    } else if (i0 >= NUM_NODES - NUM_FILLER) {
        sxo.x = sx.x * fscale; sxo.y = sx.y * fscale;
        sxo.z = sx.z * fscale; sxo.w = sx.w * fscale;
        syo.x = sy.x * fscale; syo.y = sy.y * fscale;
        syo.z = sy.z * fscale; syo.w = sy.w * fscale;
    }

    out[g]                  = xo;
    out[OUT_GROUPS + g]     = yo;
    out[2 * OUT_GROUPS + g] = sxo;
    out[3 * OUT_GROUPS + g] = syo;
}

// ---------------- launch (PDL chain) ----------------------------------------
extern "C" void kernel_launch(void* const* d_in, const int* in_sizes, int n_in,
                              void* d_out, int out_size) {
    const float* pos         = (const float*)d_in[0];
    const float* pin_pos     = (const float*)d_in[1];
    const float* node_size_x = (const float*)d_in[2];
    const float* node_size_y = (const float*)d_in[3];
    const int*   flat_netpin = (const int*)d_in[4];
    float* out = (float*)d_out;

    const float4* pos4  = (const float4*)pos;
    const float4* posy4 = (const float4*)(pos + NUM_NODES);
    const float4* nsx4  = (const float4*)node_size_x;
    const float4* nsy4  = (const float4*)node_size_y;
    const float4* px4   = (const float4*)pin_pos;
    const float4* py4   = (const float4*)(pin_pos + NUM_PINS);

    k_prep<<<(PIN_GROUPS + 255) / 256, 256>>>(px4, py4);

    cudaLaunchAttribute attr[1];
    attr[0].id = cudaLaunchAttributeProgrammaticStreamSerialization;
    attr[0].val.programmaticStreamSerializationAllowed = 1;

    {
        cudaLaunchConfig_t cfg = {};
        cfg.gridDim = dim3(NET_BLOCKS + AREA_BLOCKS);
        cfg.blockDim = dim3(256);
        cfg.attrs = attr; cfg.numAttrs = 1;
        cudaLaunchKernelEx(&cfg, k_fused, flat_netpin, pos4, posy4, nsx4, nsy4);
    }
    {
        cudaLaunchConfig_t cfg = {};
        cfg.gridDim = dim3(NB);
        cfg.blockDim = dim3(NB);
        cfg.attrs = attr; cfg.numAttrs = 1;
        cudaLaunchKernelEx(&cfg, k_scan);
    }
    {
        cudaLaunchConfig_t cfg = {};
        cfg.gridDim = dim3((OUT_GROUPS + 255) / 256);
        cfg.blockDim = dim3(256);
        cfg.attrs = attr; cfg.numAttrs = 1;
        cudaLaunchKernelEx(&cfg, k_output, pos4, posy4, nsx4, nsy4,
                           (float4*)out);
    }
}

// round 17
// speedup vs baseline: 1.0722x; 1.0009x over previous
#include <cuda_runtime.h>
#include <math.h>

#define NUM_NODES   2000000
#define NUM_MOVABLE 1500000
#define NUM_FILLER  400000
#define NUM_NETS    1500000
#define NUM_PINS    6000000
#define NB          512
#define NBP         513          // padded dim for diff map
#define BIN_W       1.953125f
#define UNIT_CAP    1.5f
#define EPSF        1e-6f

// ---------------- scratch (static device globals; no allocations) -----------
__device__ float2 g_pin_xy[NUM_PINS];   // interleaved (x,y) per physical pin
__device__ float2 g_D[NBP * NBP];       // diff map [y*NBP + x], padded
__device__ float2 g_Sf[NB * NB];        // scan_x result [y*NB + x] (float2)
__device__ float  g_ratio[NB * NB];     // ratio map [x*NB + y]
__device__ float  g_binarea[NB * NB];   // per-bin movable area [x*NB + y]
__device__ double g_sum_area;
__device__ double g_sum_route;
__device__ double g_sum_filler;
__device__ unsigned int g_bar;          // device-wide barrier counter

__device__ __forceinline__ int bin_of(float v) {
    int b = (int)floorf(v / BIN_W);
    return min(max(b, 0), NB - 1);
}

// one L2 atomic op for the adjacent (dh, dv) pair
__device__ __forceinline__ void red2(float2* addr, float a, float b) {
    asm volatile("red.global.add.v2.f32 [%0], {%1, %2};"
                 :: "l"(addr), "f"(a), "f"(b) : "memory");
}

// ---------------- kernel 1: pin transpose + zero scratch --------------------
#define PIN_GROUPS (NUM_PINS / 4)          // 1.5M
__global__ void k_prep(const float4* __restrict__ px4,
                       const float4* __restrict__ py4) {
    int g = blockIdx.x * blockDim.x + threadIdx.x;
    if (g < PIN_GROUPS) {
        float4 x = px4[g];
        float4 y = py4[g];
        float4* out = (float4*)g_pin_xy;
        out[g * 2]     = make_float4(x.x, y.x, x.y, y.y);
        out[g * 2 + 1] = make_float4(x.z, y.z, x.w, y.w);
    }
    if (g < NBP * NBP) g_D[g] = make_float2(0.0f, 0.0f);
    if (g < NB * NB)   g_binarea[g] = 0.0f;
    if (g == 0) {
        g_sum_area   = 0.0;
        g_sum_route  = 0.0;
        g_sum_filler = 0.0;
        g_bar        = 0u;
    }
}

// ---------------- kernel 2: fused nets-scatter + node sums (PDL dep) --------
#define NET_PER_THREAD 2
#define NET_THREADS    (NUM_NETS / NET_PER_THREAD)          // 750000
#define NET_BLOCKS     ((NET_THREADS + 255) / 256)          // 2930
#define AREA_GROUPS    (NUM_NODES / 4)                      // 500000
#define AREA_BLOCKS    ((AREA_GROUPS + 255) / 256)          // 1954

__device__ __forceinline__ void net_scatter(int4 fp) {
    float2 p0 = __ldg(&g_pin_xy[fp.x]);
    float2 p1 = __ldg(&g_pin_xy[fp.y]);
    float2 p2 = __ldg(&g_pin_xy[fp.z]);
    float2 p3 = __ldg(&g_pin_xy[fp.w]);

    float xl = fminf(fminf(p0.x, p1.x), fminf(p2.x, p3.x));
    float xh = fmaxf(fmaxf(p0.x, p1.x), fmaxf(p2.x, p3.x));
    float yl = fminf(fminf(p0.y, p1.y), fminf(p2.y, p3.y));
    float yh = fmaxf(fmaxf(p0.y, p1.y), fmaxf(p2.y, p3.y));

    float bw = xh - xl;
    float bh = yh - yl;
    float barea = fmaxf(bw * bh, EPSF);
    float dh = bw / barea;
    float dv = bh / barea;

    int blx = bin_of(xl);
    int bhx = bin_of(xh) + 1;   // up to 512: lands in padding (never read)
    int bly = bin_of(yl);
    int bhy = bin_of(yh) + 1;

    red2(&g_D[bly * NBP + blx],  dh,  dv);
    red2(&g_D[bly * NBP + bhx], -dh, -dv);
    red2(&g_D[bhy * NBP + blx], -dh, -dv);
    red2(&g_D[bhy * NBP + bhx],  dh,  dv);
}

__global__ void k_fused(const int* __restrict__ flat_netpin,
                        const float4* __restrict__ pos4,
                        const float4* __restrict__ posy4,
                        const float4* __restrict__ nsx4,
                        const float4* __restrict__ nsy4) {
    if (blockIdx.x < NET_BLOCKS) {
        int gid = blockIdx.x * blockDim.x + threadIdx.x;
        int n0 = gid * NET_PER_THREAD;
        // prelude: netpin indices are inputs, independent of k_prep
        int4 a = make_int4(0, 0, 0, 0), b = make_int4(0, 0, 0, 0);
        if (n0 < NUM_NETS) {
            const int4* fp4 = (const int4*)flat_netpin;
            a = fp4[n0];
            b = fp4[n0 + 1];
        }
        cudaGridDependencySynchronize();   // wait for g_pin_xy / g_D
        if (n0 >= NUM_NETS) return;
        net_scatter(a);
        net_scatter(b);
        return;
    }

    // ---- area part: prelude loads inputs, sync before scratch atomics ----
    int g = (blockIdx.x - NET_BLOCKS) * blockDim.x + threadIdx.x;
    double la = 0.0, lf = 0.0;
    float a0 = 0.f, a1 = 0.f, a2 = 0.f, a3 = 0.f;
    int b0 = 0, b1 = 0, b2 = 0, b3 = 0;
    bool movable = false;
    if (g < AREA_GROUPS) {
        int i0 = g * 4;
        float4 sx = nsx4[g];
        float4 sy = nsy4[g];
        if (i0 < NUM_MOVABLE) {
            float4 px = pos4[g];
            float4 py = posy4[g];
            a0 = sx.x * sy.x; a1 = sx.y * sy.y;
            a2 = sx.z * sy.z; a3 = sx.w * sy.w;
            b0 = bin_of(px.x + 0.5f * sx.x) * NB + bin_of(py.x + 0.5f * sy.x);
            b1 = bin_of(px.y + 0.5f * sx.y) * NB + bin_of(py.y + 0.5f * sy.y);
            b2 = bin_of(px.z + 0.5f * sx.z) * NB + bin_of(py.z + 0.5f * sy.z);
            b3 = bin_of(px.w + 0.5f * sx.w) * NB + bin_of(py.w + 0.5f * sy.w);
            la = (double)a0 + (double)a1 + (double)a2 + (double)a3;
            movable = true;
        } else if (i0 >= NUM_NODES - NUM_FILLER) {
            lf = (double)(sx.x * sy.x) + (double)(sx.y * sy.y)
               + (double)(sx.z * sy.z) + (double)(sx.w * sy.w);
        }
    }
    cudaGridDependencySynchronize();   // wait for zeroed g_binarea / sums
    if (movable) {
        atomicAdd(&g_binarea[b0], a0);
        atomicAdd(&g_binarea[b1], a1);
        atomicAdd(&g_binarea[b2], a2);
        atomicAdd(&g_binarea[b3], a3);
    }
    for (int off = 16; off > 0; off >>= 1) {
        la += __shfl_down_sync(0xFFFFFFFFu, la, off);
        lf += __shfl_down_sync(0xFFFFFFFFu, lf, off);
    }
    if ((threadIdx.x & 31) == 0) {
        if (la != 0.0) atomicAdd(&g_sum_area,   la);
        if (lf != 0.0) atomicAdd(&g_sum_filler, lf);
    }
}

// ---------------- block-wide inclusive scan (512 threads, double2) ----------
__device__ __forceinline__ double2 block_scan_512(double2 v) {
    __shared__ double2 partials[16];
    int lane = threadIdx.x & 31;
    int warp = threadIdx.x >> 5;
    #pragma unroll
    for (int off = 1; off < 32; off <<= 1) {
        double ax = __shfl_up_sync(0xFFFFFFFFu, v.x, off);
        double ay = __shfl_up_sync(0xFFFFFFFFu, v.y, off);
        if (lane >= off) { v.x += ax; v.y += ay; }
    }
    if (lane == 31) partials[warp] = v;
    __syncthreads();
    if (warp == 0 && lane < 16) {
        double2 p = partials[lane];
        #pragma unroll
        for (int off = 1; off < 16; off <<= 1) {
            double ax = __shfl_up_sync(0x0000FFFFu, p.x, off);
            double ay = __shfl_up_sync(0x0000FFFFu, p.y, off);
            if (lane >= off) { p.x += ax; p.y += ay; }
        }
        partials[lane] = p;
    }
    __syncthreads();
    if (warp > 0) {
        double2 p = partials[warp - 1];
        v.x += p.x; v.y += p.y;
    }
    return v;
}

// ---------------- kernel 3: merged scan_x + scan_y (one wave + barrier) -----
__global__ void __launch_bounds__(512, 4) k_scan() {
    cudaGridDependencySynchronize();   // wait for g_D / g_binarea
    int b = blockIdx.x;
    int t = threadIdx.x;

    // ---- phase 1: inclusive scan along x for row y=b (fully coalesced) ----
    {
        float2 d = g_D[b * NBP + t];
        double2 v = make_double2((double)d.x, (double)d.y);
        v = block_scan_512(v);
        g_Sf[b * NB + t] = make_float2((float)v.x, (float)v.y);
    }
    __syncthreads();

    // ---- device-wide barrier (threadfence-reduction pattern) ----
    if (t == 0) {
        __threadfence();
        atomicAdd(&g_bar, 1u);
        while (atomicAdd(&g_bar, 0u) < NB) __nanosleep(64);
        __threadfence();
    }
    __syncthreads();

    // ---- phase 2: scan along y for column x=b + ratio + dot ----
    {
        __shared__ double s_route[16];
        int x = b;
        int y = t;
        int lane = t & 31;
        int warp = t >> 5;

        float2 d = g_Sf[y * NB + x];
        double2 v = make_double2((double)d.x, (double)d.y);
        v = block_scan_512(v);
        float uh = (float)v.x / UNIT_CAP;
        float uv = (float)v.y / UNIT_CAP;
        float r = fminf(fmaxf(fmaxf(uh, uv), 0.5f), 2.0f);
        int idx = x * NB + y;
        g_ratio[idx] = r;

        // ratio is written; allow k_output to launch and run its prelude.
        // (all blocks are past the spin barrier here -> no residency deadlock)
        cudaTriggerProgrammaticLaunchCompletion();

        double lr = (double)(r * g_binarea[idx]);
        for (int off = 16; off > 0; off >>= 1)
            lr += __shfl_down_sync(0xFFFFFFFFu, lr, off);
        if (lane == 0) s_route[warp] = lr;
        __syncthreads();
        if (warp == 0) {
            double tt = (lane < 16) ? s_route[lane] : 0.0;
            for (int off = 8; off > 0; off >>= 1)
                tt += __shfl_down_sync(0xFFFFFFFFu, tt, off);
            if (lane == 0 && tt != 0.0) atomicAdd(&g_sum_route, tt);
        }
    }
}

// ---------------- kernel 4: outputs (prelude loads, then sync) --------------
#define OUT_GROUPS (NUM_NODES / 4)        // 500000

__global__ void k_output(const float4* __restrict__ pos4,
                         const float4* __restrict__ posy4,
                         const float4* __restrict__ nsx4,
                         const float4* __restrict__ nsy4,
                         float4* __restrict__ out) {
    int g = blockIdx.x * blockDim.x + threadIdx.x;
    bool live = (g < OUT_GROUPS);
    int i0 = g * 4;

    // prelude: pure-input loads + bin index math (independent of k_scan)
    float4 x = make_float4(0, 0, 0, 0), y = x, sx = x, sy = x;
    int r0i = 0, r1i = 0, r2i = 0, r3i = 0;
    if (live) {
        x  = pos4[g];
        y  = posy4[g];
        sx = nsx4[g];
        sy = nsy4[g];
        if (i0 < NUM_MOVABLE) {
            r0i = bin_of(x.x + 0.5f * sx.x) * NB + bin_of(y.x + 0.5f * sy.x);
            r1i = bin_of(x.y + 0.5f * sx.y) * NB + bin_of(y.y + 0.5f * sy.y);
            r2i = bin_of(x.z + 0.5f * sx.z) * NB + bin_of(y.z + 0.5f * sy.z);
            r3i = bin_of(x.w + 0.5f * sx.w) * NB + bin_of(y.w + 0.5f * sy.w);
        }
    }

    cudaGridDependencySynchronize();   // wait for g_ratio + sums
    if (!live) return;

    float sum_area   = (float)g_sum_area;
    float sum_route  = (float)g_sum_route;
    float sum_filler = (float)g_sum_filler;
    float max_total  = sum_area + sum_filler;
    float scale  = fminf(1.0f, max_total / fmaxf(sum_route, EPSF));
    float fscale = sqrtf(fmaxf(max_total - sum_route * scale, 0.0f) /
                         fmaxf(sum_filler, EPSF));

    float4 xo = x, yo = y, sxo = sx, syo = sy;

    if (i0 < NUM_MOVABLE) {
        float r0 = __ldg(&g_ratio[r0i]);
        float r1 = __ldg(&g_ratio[r1i]);
        float r2 = __ldg(&g_ratio[r2i]);
        float r3 = __ldg(&g_ratio[r3i]);

        float s0 = sqrtf(r0 * scale), s1 = sqrtf(r1 * scale);
        float s2 = sqrtf(r2 * scale), s3 = sqrtf(r3 * scale);
        float nx0 = sx.x * s0, ny0 = sy.x * s0;
        float nx1 = sx.y * s1, ny1 = sy.y * s1;
        float nx2 = sx.z * s2, ny2 = sy.z * s2;
        float nx3 = sx.w * s3, ny3 = sy.w * s3;
        xo.x = x.x + 0.5f * (sx.x - nx0); yo.x = y.x + 0.5f * (sy.x - ny0);
        xo.y = x.y + 0.5f * (sx.y - nx1); yo.y = y.y + 0.5f * (sy.y - ny1);
        xo.z = x.z + 0.5f * (sx.z - nx2); yo.z = y.z + 0.5f * (sy.z - ny2);
        xo.w = x.w + 0.5f * (sx.w - nx3); yo.w = y.w + 0.5f * (sy.w - ny3);
        sxo = make_float4(nx0, nx1, nx2, nx3);
        syo = make_float4(ny0, ny1, ny2, ny3);
    } else if (i0 >= NUM_NODES - NUM_FILLER) {
        sxo.x = sx.x * fscale; sxo.y = sx.y * fscale;
        sxo.z = sx.z * fscale; sxo.w = sx.w * fscale;
        syo.x = sy.x * fscale; syo.y = sy.y * fscale;
        syo.z = sy.z * fscale; syo.w = sy.w * fscale;
    }

    out[g]                  = xo;
    out[OUT_GROUPS + g]     = yo;
    out[2 * OUT_GROUPS + g] = sxo;
    out[3 * OUT_GROUPS + g] = syo;
}

// ---------------- launch (PDL chain) ----------------------------------------
extern "C" void kernel_launch(void* const* d_in, const int* in_sizes, int n_in,
                              void* d_out, int out_size) {
    const float* pos         = (const float*)d_in[0];
    const float* pin_pos     = (const float*)d_in[1];
    const float* node_size_x = (const float*)d_in[2];
    const float* node_size_y = (const float*)d_in[3];
    const int*   flat_netpin = (const int*)d_in[4];
    float* out = (float*)d_out;

    const float4* pos4  = (const float4*)pos;
    const float4* posy4 = (const float4*)(pos + NUM_NODES);
    const float4* nsx4  = (const float4*)node_size_x;
    const float4* nsy4  = (const float4*)node_size_y;
    const float4* px4   = (const float4*)pin_pos;
    const float4* py4   = (const float4*)(pin_pos + NUM_PINS);

    k_prep<<<(PIN_GROUPS + 255) / 256, 256>>>(px4, py4);

    cudaLaunchAttribute attr[1];
    attr[0].id = cudaLaunchAttributeProgrammaticStreamSerialization;
    attr[0].val.programmaticStreamSerializationAllowed = 1;

    {
        cudaLaunchConfig_t cfg = {};
        cfg.gridDim = dim3(NET_BLOCKS + AREA_BLOCKS);
        cfg.blockDim = dim3(256);
        cfg.attrs = attr; cfg.numAttrs = 1;
        cudaLaunchKernelEx(&cfg, k_fused, flat_netpin, pos4, posy4, nsx4, nsy4);
    }
    {
        cudaLaunchConfig_t cfg = {};
        cfg.gridDim = dim3(NB);
        cfg.blockDim = dim3(NB);
        cfg.attrs = attr; cfg.numAttrs = 1;
        cudaLaunchKernelEx(&cfg, k_scan);
    }
    {
        cudaLaunchConfig_t cfg = {};
        cfg.gridDim = dim3((OUT_GROUPS + 255) / 256);
        cfg.blockDim = dim3(256);
        cfg.attrs = attr; cfg.numAttrs = 1;
        cudaLaunchKernelEx(&cfg, k_output, pos4, posy4, nsx4, nsy4,
                           (float4*)out);
    }
}